// round 7
// baseline (speedup 1.0000x reference)
#include <cuda_runtime.h>
#include <cuda_fp16.h>

#define NN 100000
#define NNP 100096            // padded to multiple of 128 (1564 * 64)
#define NE 1600000
#define CHUNK 512
#define NCH ((NN + CHUNK - 1) / CHUNK)   // 196

// ---- scratch (static device globals; zero-initialized; no allocation allowed) ----
__device__ __half g_xh[NNP * 128];      // x hi/lo (fp16 split, padded)
__device__ __half g_xl[NNP * 128];
__device__ __half g_hNh[NNP * 256];     // aggregated neighbor feats hi/lo
__device__ __half g_hNl[NNP * 256];
__device__ float  g_hAf[NNP * 256];     // layer-1 output full (agg input for L2)
__device__ __half g_hAh[NNP * 256];
__device__ __half g_hAl[NNP * 256];
__device__ __half g_hBh[NNP * 256];     // layer-2 output (hi/lo only)
__device__ __half g_hBl[NNP * 256];
__device__ float  g_z[NNP * 128];       // layer-3 GEMM out: [z_self | z_neigh]
__device__ __half g_W1h[256 * 256];
__device__ __half g_W1l[256 * 256];
__device__ __half g_W2h[256 * 512];
__device__ __half g_W2l[256 * 512];
__device__ __half g_W3h[128 * 256];    // stacked [W3_self; W3_neigh]
__device__ __half g_W3l[128 * 256];
__device__ int   g_deg[NN];
__device__ int   g_rowptr[NN + 1];
__device__ int   g_cursor[NN];
__device__ int   g_csr[NE];

// ======================= helpers =======================

__device__ __forceinline__ void splith(float v, __half& h, __half& l) {
    h = __float2half_rn(v);
    l = __float2half_rn(v - __half2float(h));
}

__device__ __forceinline__ unsigned smem_u32(const void* p) {
    unsigned a;
    asm("{ .reg .u64 t; cvta.to.shared.u64 t, %1; cvt.u32.u64 %0, t; }" : "=r"(a) : "l"(p));
    return a;
}

__device__ __forceinline__ void cp16(unsigned dst, const void* src) {
    asm volatile("cp.async.cg.shared.global [%0], [%1], 16;" :: "r"(dst), "l"(src));
}
#define CP_COMMIT() asm volatile("cp.async.commit_group;" ::: "memory")
#define CP_WAIT1()  asm volatile("cp.async.wait_group 1;" ::: "memory")

__device__ __forceinline__ void mma16(float* c, const unsigned* a, const unsigned* b) {
    asm volatile(
        "mma.sync.aligned.m16n8k16.row.col.f32.f16.f16.f32 "
        "{%0,%1,%2,%3}, {%4,%5,%6,%7}, {%8,%9}, {%0,%1,%2,%3};"
        : "+f"(c[0]), "+f"(c[1]), "+f"(c[2]), "+f"(c[3])
        : "r"(a[0]), "r"(a[1]), "r"(a[2]), "r"(a[3]), "r"(b[0]), "r"(b[1]));
}

__device__ __forceinline__ void ldm_x4(unsigned& r0, unsigned& r1, unsigned& r2,
                                       unsigned& r3, unsigned addr) {
    asm volatile("ldmatrix.sync.aligned.m8n8.x4.shared.b16 {%0,%1,%2,%3}, [%4];"
                 : "=r"(r0), "=r"(r1), "=r"(r2), "=r"(r3) : "r"(addr));
}

// ======================= fused prep: x split, W splits, deg zero =======================
// segment layout: [0, NX): x | [NX, +65536): W1 | +131072: W2 | +32768: W3 | +NN: deg

__global__ void k_prep(const float* __restrict__ x, const float* __restrict__ W1,
                       const float* __restrict__ W2, const float* __restrict__ W3) {
    const int NX = NN * 32;                    // float4 count of x
    long i = (long)blockIdx.x * blockDim.x + threadIdx.x;
    if (i < NX) {
        float4 v = ((const float4*)x)[i];
        __half h0, h1, h2, h3, l0, l1, l2, l3;
        splith(v.x, h0, l0); splith(v.y, h1, l1);
        splith(v.z, h2, l2); splith(v.w, h3, l3);
        ((__half2*)g_xh)[2 * i]     = __halves2half2(h0, h1);
        ((__half2*)g_xh)[2 * i + 1] = __halves2half2(h2, h3);
        ((__half2*)g_xl)[2 * i]     = __halves2half2(l0, l1);
        ((__half2*)g_xl)[2 * i + 1] = __halves2half2(l2, l3);
        return;
    }
    i -= NX;
    if (i < 256 * 256) {
        __half h, l; splith(W1[i], h, l);
        g_W1h[i] = h; g_W1l[i] = l;
        return;
    }
    i -= 256 * 256;
    if (i < 256 * 512) {
        __half h, l; splith(W2[i], h, l);
        g_W2h[i] = h; g_W2l[i] = l;
        return;
    }
    i -= 256 * 512;
    if (i < 128 * 256) {
        int r = (int)(i >> 8), c = (int)(i & 255);
        float v = (r < 64) ? W3[r * 512 + c] : W3[(r - 64) * 512 + 256 + c];
        __half h, l; splith(v, h, l);
        g_W3h[i] = h; g_W3l[i] = l;
        return;
    }
    i -= 128 * 256;
    if (i < NN) g_deg[i] = 0;
}

#define PREP_TOTAL (NN * 32 + 256 * 256 + 256 * 512 + 128 * 256 + NN)

// ======================= CSR build =======================

__global__ void k_hist(const int* __restrict__ dst) {
    int e = blockIdx.x * blockDim.x + threadIdx.x;
    if (e < NE) atomicAdd(&g_deg[dst[e]], 1);
}

// single block: chunk sums -> serial scan -> fill rowptr/cursor
__global__ void k_csr_mid() {
    __shared__ int ssum[NCH];
    int t = threadIdx.x;
    if (t < NCH) {
        int base = t * CHUNK;
        int end = base + CHUNK; if (end > NN) end = NN;
        int s = 0;
        for (int i = base; i < end; i++) s += g_deg[i];
        ssum[t] = s;
    }
    __syncthreads();
    if (t == 0) {
        int run = 0;
        for (int c = 0; c < NCH; c++) {
            int v = ssum[c];
            ssum[c] = run;
            run += v;
        }
        g_rowptr[NN] = run;
    }
    __syncthreads();
    if (t < NCH) {
        int base = t * CHUNK;
        int end = base + CHUNK; if (end > NN) end = NN;
        int run = ssum[t];
        for (int i = base; i < end; i++) {
            g_rowptr[i] = run;
            g_cursor[i] = run;
            run += g_deg[i];
        }
    }
}

__global__ void k_scatter(const int* __restrict__ src, const int* __restrict__ dst) {
    int e = blockIdx.x * blockDim.x + threadIdx.x;
    if (e < NE) {
        int p = atomicAdd(&g_cursor[dst[e]], 1);
        g_csr[p] = src[e];
    }
}

// ======================= aggregation (mean of neighbor features) =======================
// One warp per node; fp32 gather (UNR edges in flight); fp16 hi/lo split output.

template <int DV, int UNR>
__global__ void k_agg(const float* __restrict__ h, __half* __restrict__ oh,
                      __half* __restrict__ ol) {
    int gwarp = (blockIdx.x * blockDim.x + threadIdx.x) >> 5;
    int lane = threadIdx.x & 31;
    if (gwarp >= NN) return;

    int s0 = g_rowptr[gwarp];
    int s1 = g_rowptr[gwarp + 1];

    float4 acc[DV];
#pragma unroll
    for (int j = 0; j < DV; j++) acc[j] = make_float4(0.f, 0.f, 0.f, 0.f);

    const int stride4 = DV * 32;
    const float4* __restrict__ hv = (const float4*)h;

    int e = s0;
    for (; e + UNR <= s1; e += UNR) {
        float4 v[UNR][DV];
#pragma unroll
        for (int u = 0; u < UNR; u++) {
            const float4* r = hv + (long)g_csr[e + u] * stride4;
#pragma unroll
            for (int j = 0; j < DV; j++) v[u][j] = r[lane + 32 * j];
        }
#pragma unroll
        for (int u = 0; u < UNR; u++)
#pragma unroll
            for (int j = 0; j < DV; j++) {
                acc[j].x += v[u][j].x; acc[j].y += v[u][j].y;
                acc[j].z += v[u][j].z; acc[j].w += v[u][j].w;
            }
    }
    for (; e < s1; e++) {
        const float4* r = hv + (long)g_csr[e] * stride4;
#pragma unroll
        for (int j = 0; j < DV; j++) {
            float4 v = r[lane + 32 * j];
            acc[j].x += v.x; acc[j].y += v.y; acc[j].z += v.z; acc[j].w += v.w;
        }
    }

    int deg = s1 - s0;
    float inv = 1.0f / (float)(deg > 0 ? deg : 1);
    __half2* ovh = (__half2*)oh + (long)gwarp * (stride4 * 2);
    __half2* ovl = (__half2*)ol + (long)gwarp * (stride4 * 2);
#pragma unroll
    for (int j = 0; j < DV; j++) {
        float4 v;
        v.x = acc[j].x * inv; v.y = acc[j].y * inv;
        v.z = acc[j].z * inv; v.w = acc[j].w * inv;
        __half h0, h1, h2, h3, l0, l1, l2, l3;
        splith(v.x, h0, l0); splith(v.y, h1, l1);
        splith(v.z, h2, l2); splith(v.w, h3, l3);
        int f = lane + 32 * j;
        ovh[2 * f]     = __halves2half2(h0, h1);
        ovh[2 * f + 1] = __halves2half2(h2, h3);
        ovl[2 * f]     = __halves2half2(l0, l1);
        ovl[2 * f + 1] = __halves2half2(l2, l3);
    }
}

// ======================= layer-3 final: out = z_self + mean(z_neigh) + b =======================
// z: [NNP, 128], cols 0-63 self, 64-127 neighbor. One warp per node, 2 cols/lane.

__global__ void k_agg_out(const float* __restrict__ z, const float* __restrict__ b3,
                          float* __restrict__ out) {
    int gwarp = (blockIdx.x * blockDim.x + threadIdx.x) >> 5;
    int lane = threadIdx.x & 31;
    if (gwarp >= NN) return;

    int s0 = g_rowptr[gwarp];
    int s1 = g_rowptr[gwarp + 1];

    float2 acc = make_float2(0.f, 0.f);
    const float2* zn = (const float2*)(z + 64);
    int e = s0;
    for (; e + 3 < s1; e += 4) {
        float2 v0 = zn[(long)g_csr[e] * 64 + lane];
        float2 v1 = zn[(long)g_csr[e + 1] * 64 + lane];
        float2 v2 = zn[(long)g_csr[e + 2] * 64 + lane];
        float2 v3 = zn[(long)g_csr[e + 3] * 64 + lane];
        acc.x += (v0.x + v1.x) + (v2.x + v3.x);
        acc.y += (v0.y + v1.y) + (v2.y + v3.y);
    }
    for (; e < s1; e++) {
        float2 v = zn[(long)g_csr[e] * 64 + lane];
        acc.x += v.x; acc.y += v.y;
    }
    int deg = s1 - s0;
    float inv = 1.0f / (float)(deg > 0 ? deg : 1);

    float2 self = ((const float2*)z)[(long)gwarp * 64 + lane];
    float2 bb = ((const float2*)b3)[lane];
    float2 r;
    r.x = self.x + acc.x * inv + bb.x;
    r.y = self.y + acc.y * inv + bb.y;
    ((float2*)out)[(long)gwarp * 32 + lane] = r;
}

// ======================= fp16 3-product mma.sync concat-GEMM =======================
// C[M, N_OUT] = [A1 | A2] @ W^T (+ bias, optional ReLU), as
//   A_hi.B_hi + A_hi.B_lo + A_lo.B_hi  (fp16 operands, fp32 accumulate)
// Block: 64(M) x 128(N), 256 threads (8 warps, 2Mx4N), warp tile 32x32.
// K chunks of 64 halves, double-buffered cp.async. Smem stride 72 halves.
// Small tiles -> 3128-block grid, ~3% wave tail; 4 CTAs/SM by smem.

template <int N_OUT, int K, bool CONCAT, bool RELU, int OMODE>
__global__ void __launch_bounds__(256)
k_mma(const __half* __restrict__ A1h, const __half* __restrict__ A2h,
      const __half* __restrict__ A1l, const __half* __restrict__ A2l,
      const __half* __restrict__ Wh,  const __half* __restrict__ Wl,
      const float* __restrict__ bias,
      float* __restrict__ Cf, __half* __restrict__ Ch, __half* __restrict__ Cl) {
    constexpr int BM = 64;
    constexpr int BN = 128;
    constexpr int D = CONCAT ? K / 2 : K;      // source row width
    constexpr int NCP = K / 64;                // chunks per phase
    constexpr int NC3 = 3 * NCP;
    constexpr int NT = 4;                      // n-tiles of 8 per warp (32 wide)
    constexpr int SH = 72;                     // smem stride in halves
    constexpr int A_BYTES = BM * SH * 2;       // 9216
    constexpr int B_BYTES = BN * SH * 2;       // 18432
    constexpr int STAGE_B = A_BYTES + B_BYTES; // 27648

    extern __shared__ char smem_raw[];
    const unsigned sbase = smem_u32(smem_raw);

    const int tid = threadIdx.x;
    const int wid = tid >> 5;
    const int lane = tid & 31;
    const int wm = wid & 1;                    // 2 m-warps
    const int wn = wid >> 1;                   // 4 n-warps
    const int n0 = blockIdx.x * BN;
    const int m0 = blockIdx.y * BM;

    const int lr = lane >> 2;
    const int lc = lane & 3;

    // ldmatrix per-lane byte offsets
    unsigned offA[2], offB[2];
#pragma unroll
    for (int mt = 0; mt < 2; mt++) {
        int row = wm * 32 + mt * 16 + (lane & 15);
        int col = (lane >> 4) * 8;
        offA[mt] = (unsigned)(row * SH + col) * 2;
    }
#pragma unroll
    for (int p = 0; p < 2; p++) {
        int row = wn * 32 + p * 16 + (lane & 7) + ((lane >> 4) & 1) * 8;
        int col = ((lane >> 3) & 1) * 8;
        offB[p] = (unsigned)(A_BYTES) + (unsigned)(row * SH + col) * 2;
    }

    float acc[2][NT][4];
#pragma unroll
    for (int mt = 0; mt < 2; mt++)
#pragma unroll
        for (int nt = 0; nt < NT; nt++)
#pragma unroll
            for (int q = 0; q < 4; q++) acc[mt][nt][q] = 0.f;

    auto load_chunk = [&](int j, int s) {
        unsigned base = sbase + s * STAGE_B;
        int p = j / NCP;                       // 0: hi.hi, 1: hi.lo, 2: lo.hi
        int kc = j - p * NCP;
        int k0 = kc * 64;
        const __half* A;
        int ka;
        if (CONCAT && k0 >= D) {
            A = (p < 2) ? A2h : A2l; ka = k0 - D;
        } else {
            A = (p < 2) ? A1h : A1l; ka = k0;
        }
        const __half* B = (p == 1) ? Wl : Wh;
        // A tile: 64 rows x 8 cp16 = 512; 2 per thread
#pragma unroll
        for (int q = 0; q < 2; q++) {
            int idx = tid + 256 * q;
            int row = idx >> 3, c8 = idx & 7;
            cp16(base + (unsigned)(row * (SH * 2) + c8 * 16),
                 A + (long)(m0 + row) * D + ka + c8 * 8);
        }
        // B tile: 128 rows x 8 cp16 = 1024; 4 per thread
#pragma unroll
        for (int q = 0; q < 4; q++) {
            int idx = tid + 256 * q;
            int n = idx >> 3, c8 = idx & 7;
            cp16(base + (unsigned)(A_BYTES + n * (SH * 2) + c8 * 16),
                 B + (long)(n0 + n) * K + k0 + c8 * 8);
        }
        CP_COMMIT();
    };

    load_chunk(0, 0);
    load_chunk(1, 1);

#pragma unroll 1
    for (int i = 0; i < NC3; i++) {
        int s = i & 1;
        CP_WAIT1();
        __syncthreads();

        unsigned stage = sbase + s * STAGE_B;

#pragma unroll
        for (int ks = 0; ks < 4; ks++) {
            unsigned kso = ks * 32;            // 16 halves
            unsigned a[2][4];
#pragma unroll
            for (int mt = 0; mt < 2; mt++)
                ldm_x4(a[mt][0], a[mt][1], a[mt][2], a[mt][3],
                       stage + offA[mt] + kso);
            unsigned b[NT][2];
#pragma unroll
            for (int p = 0; p < 2; p++)
                ldm_x4(b[2 * p][0], b[2 * p][1], b[2 * p + 1][0], b[2 * p + 1][1],
                       stage + offB[p] + kso);
#pragma unroll
            for (int mt = 0; mt < 2; mt++)
#pragma unroll
                for (int nt = 0; nt < NT; nt++)
                    mma16(acc[mt][nt], a[mt], b[nt]);
        }

        __syncthreads();
        if (i + 2 < NC3) load_chunk(i + 2, s);
    }

    // epilogue
#pragma unroll
    for (int mt = 0; mt < 2; mt++) {
#pragma unroll
        for (int nt = 0; nt < NT; nt++) {
            int n = n0 + wn * 32 + nt * 8 + lc * 2;
            float b0 = 0.f, b1 = 0.f;
            if (OMODE != 0) { b0 = bias[n]; b1 = bias[n + 1]; }
            int r0 = m0 + wm * 32 + mt * 16 + lr;
#pragma unroll
            for (int h = 0; h < 2; h++) {
                int r = r0 + h * 8;
                if (r < NN) {
                    float v0 = acc[mt][nt][2 * h + 0] + b0;
                    float v1 = acc[mt][nt][2 * h + 1] + b1;
                    if (RELU) { v0 = v0 > 0.f ? v0 : 0.f; v1 = v1 > 0.f ? v1 : 0.f; }
                    long off = (long)r * N_OUT + n;
                    if (OMODE == 0 || OMODE == 1)
                        *(float2*)(Cf + off) = make_float2(v0, v1);
                    if (OMODE == 1 || OMODE == 2) {
                        __half h0, h1, l0, l1;
                        splith(v0, h0, l0); splith(v1, h1, l1);
                        ((__half2*)Ch)[off >> 1] = __halves2half2(h0, h1);
                        ((__half2*)Cl)[off >> 1] = __halves2half2(l0, l1);
                    }
                }
            }
        }
    }
}

// ======================= launch =======================

extern "C" void kernel_launch(void* const* d_in, const int* in_sizes, int n_in,
                              void* d_out, int out_size) {
    const float* x   = (const float*)d_in[0];
    const int*   src = (const int*)d_in[1];
    const int*   dst = (const int*)d_in[2];
    const float* W1  = (const float*)d_in[3];
    const float* b1  = (const float*)d_in[4];
    const float* W2  = (const float*)d_in[5];
    const float* b2  = (const float*)d_in[6];
    const float* W3  = (const float*)d_in[7];
    const float* b3  = (const float*)d_in[8];
    float* out = (float*)d_out;

    __half *xh, *xl, *hNh, *hNl, *hAh, *hAl, *hBh, *hBl;
    __half *W1h, *W1l, *W2h, *W2l, *W3h, *W3l;
    float *hAf, *z;
    cudaGetSymbolAddress((void**)&xh, g_xh);
    cudaGetSymbolAddress((void**)&xl, g_xl);
    cudaGetSymbolAddress((void**)&hNh, g_hNh);
    cudaGetSymbolAddress((void**)&hNl, g_hNl);
    cudaGetSymbolAddress((void**)&hAf, g_hAf);
    cudaGetSymbolAddress((void**)&hAh, g_hAh);
    cudaGetSymbolAddress((void**)&hAl, g_hAl);
    cudaGetSymbolAddress((void**)&hBh, g_hBh);
    cudaGetSymbolAddress((void**)&hBl, g_hBl);
    cudaGetSymbolAddress((void**)&z, g_z);
    cudaGetSymbolAddress((void**)&W1h, g_W1h);
    cudaGetSymbolAddress((void**)&W1l, g_W1l);
    cudaGetSymbolAddress((void**)&W2h, g_W2h);
    cudaGetSymbolAddress((void**)&W2l, g_W2l);
    cudaGetSymbolAddress((void**)&W3h, g_W3h);
    cudaGetSymbolAddress((void**)&W3l, g_W3l);

    constexpr int SMB = 2 * ((64 + 128) * 72 * 2);   // 55296
    cudaFuncSetAttribute(k_mma<256, 256, true,  true,  1>,
                         cudaFuncAttributeMaxDynamicSharedMemorySize, SMB);
    cudaFuncSetAttribute(k_mma<256, 512, true,  true,  2>,
                         cudaFuncAttributeMaxDynamicSharedMemorySize, SMB);
    cudaFuncSetAttribute(k_mma<128, 256, false, false, 0>,
                         cudaFuncAttributeMaxDynamicSharedMemorySize, SMB);

    // --- fused prep + CSR build ---
    k_prep<<<(PREP_TOTAL + 255) / 256, 256>>>(x, W1, W2, W3);
    k_hist<<<(NE + 255) / 256, 256>>>(dst);
    k_csr_mid<<<1, 256>>>();
    k_scatter<<<(NE + 255) / 256, 256>>>(src, dst);

    const int AGG_BLOCKS = (NN + 7) / 8;
    const int GM = NNP / 64;   // 1564

    // layer 1: [x | agg(x)] (K=256) -> 256, ReLU
    k_agg<1, 4><<<AGG_BLOCKS, 256>>>(x, hNh, hNl);
    k_mma<256, 256, true, true, 1><<<dim3(2, GM), 256, SMB>>>(
        xh, hNh, xl, hNl, W1h, W1l, b1, hAf, hAh, hAl);

    // layer 2: [hA | agg(hA)] (K=512) -> 256, ReLU
    k_agg<2, 2><<<AGG_BLOCKS, 256>>>(hAf, hNh, hNl);
    k_mma<256, 512, true, true, 2><<<dim3(2, GM), 256, SMB>>>(
        hAh, hNh, hAl, hNl, W2h, W2l, b2, nullptr, hBh, hBl);

    // layer 3 (reordered): z = hB @ [W_self; W_neigh]^T (K=256 -> 128), then
    // out = z_self + mean(z_neigh) + b3
    k_mma<128, 256, false, false, 0><<<dim3(1, GM), 256, SMB>>>(
        hBh, hBh, hBl, hBl, W3h, W3l, nullptr, z, nullptr, nullptr);
    k_agg_out<<<AGG_BLOCKS, 256>>>(z, b3, out);
}